// round 1
// baseline (speedup 1.0000x reference)
#include <cuda_runtime.h>

// PixelShuffle / depth-to-space, R=2, feature-major grouping.
// in : [B=8, X=256, Y=256, C=256] fp32
// out: [B, 2X=512, 2Y=512, F=64]  fp32
// out[b, 2x+i, 2y+j, f] = in[b, x, y, 4f + 2i + j]
//
// 16 threads per input pixel. Thread t:
//   loads channels [16t, 16t+16) as 4x float4 (coalesced; warp reads 2KB contig)
//   holds features 4t..4t+3 for all four (i,j) phases
//   writes 4x float4, one per output row; 16 threads cover a contiguous
//   256B segment of each 64-float output row.

static constexpr int B = 8;
static constexpr int X = 256;
static constexpr int Y = 256;
static constexpr int C = 256;   // = 64 features * 4
static constexpr int THREADS = 256;

__global__ void __launch_bounds__(THREADS, 8)
pixel_shuffle_kernel(const float4* __restrict__ in, float4* __restrict__ out) {
    const long long g = (long long)blockIdx.x * THREADS + threadIdx.x;

    const int t = (int)(g & 15);          // 16-channel chunk within pixel
    const long long p = g >> 4;           // input pixel id: b*65536 + x*256 + y

    const int y = (int)(p & 255);
    const int x = (int)((p >> 8) & 255);
    const int b = (int)(p >> 16);

    // ---- load: 16 contiguous channels = 4 float4 ----
    const float4* ip = in + p * (C / 4) + t * 4;
    const float4 v0 = ip[0];
    const float4 v1 = ip[1];
    const float4 v2 = ip[2];
    const float4 v3 = ip[3];

    // L[4k + c] = channel 16t + 4k + c  (feature 4t+k, phase c = 2i + j)
    const float L0  = v0.x, L1  = v0.y, L2  = v0.z, L3  = v0.w;
    const float L4  = v1.x, L5  = v1.y, L6  = v1.z, L7  = v1.w;
    const float L8  = v2.x, L9  = v2.y, L10 = v2.z, L11 = v2.w;
    const float L12 = v3.x, L13 = v3.y, L14 = v3.z, L15 = v3.w;

    // ---- store: one float4 per (i,j) output row ----
    // out float index = ((b*512 + 2x+i)*512 + (2y+j))*64 + 4t
    // in float4 units: base = ((b*512 + 2x)*512 + 2y)*16 + t
    const long long obase =
        ((((long long)b * (2 * X) + 2 * x) * (2 * Y)) + 2 * y) * 16 + t;
    const long long ROWI = (long long)(2 * Y) * 16;  // +i stride (one output X-row)
    const long long ROWJ = 16;                       // +j stride (one output Y-row)

    out[obase]               = make_float4(L0, L4, L8,  L12);  // i=0, j=0
    out[obase + ROWJ]        = make_float4(L1, L5, L9,  L13);  // i=0, j=1
    out[obase + ROWI]        = make_float4(L2, L6, L10, L14);  // i=1, j=0
    out[obase + ROWI + ROWJ] = make_float4(L3, L7, L11, L15);  // i=1, j=1
}

extern "C" void kernel_launch(void* const* d_in, const int* in_sizes, int n_in,
                              void* d_out, int out_size) {
    (void)n_in; (void)out_size;
    const float4* in = (const float4*)d_in[0];
    float4* out = (float4*)d_out;

    const long long total_elems = (long long)in_sizes[0];   // B*X*Y*C
    const long long n_threads = total_elems / 16;           // 16 channels per thread
    const int grid = (int)((n_threads + THREADS - 1) / THREADS);

    pixel_shuffle_kernel<<<grid, THREADS>>>(in, out);
}